// round 15
// baseline (speedup 1.0000x reference)
#include <cuda_runtime.h>
#include <cuda_bf16.h>
#include <cstdint>
#include <cstddef>

#define MAXN 50000
#define MAXE 800000
#define CH   128

// ---------------------------------------------------------------------------
// Scratch (device globals)
// ---------------------------------------------------------------------------
__device__ int   g_is64;
__device__ int   g_cursor;
__device__ int   g_deg [MAXN];
__device__ int   g_cnt [MAXN];
__device__ int   g_csr_start[MAXN + 1];
__device__ int   g_csr_src[MAXE];
__device__ float g_invs[MAXN];
__device__ __nv_bfloat16 g_bufAh[(size_t)MAXN * CH];   // ping-pong bf16 buffer
__device__ __nv_bfloat16 g_bufBh[(size_t)MAXN * CH];   // ping-pong bf16 buffer
__device__ float g_gsum[128];
__device__ float g_gcnt[64];
__device__ uint32_t g_wprep[4][8192];                  // fragment-ordered B images

// ---------------------------------------------------------------------------
// helpers
// ---------------------------------------------------------------------------
__device__ __forceinline__ uint32_t smem_u32(const void* p) {
    uint32_t a;
    asm("{ .reg .u64 t; cvta.to.shared.u64 t, %1; cvt.u32.u64 %0, t; }"
        : "=r"(a) : "l"(p));
    return a;
}

#define LDMATRIX_X4(r0, r1, r2, r3, addr) \
    asm volatile("ldmatrix.sync.aligned.m8n8.x4.shared.b16 {%0,%1,%2,%3}, [%4];" \
                 : "=r"(r0), "=r"(r1), "=r"(r2), "=r"(r3) : "r"(addr))

#define MMA_BF16(d, a, b) \
    asm volatile("mma.sync.aligned.m16n8k16.row.col.f32.bf16.bf16.f32 " \
                 "{%0,%1,%2,%3}, {%4,%5,%6,%7}, {%8,%9}, {%0,%1,%2,%3};" \
                 : "+f"((d)[0]), "+f"((d)[1]), "+f"((d)[2]), "+f"((d)[3]) \
                 : "r"((a)[0]), "r"((a)[1]), "r"((a)[2]), "r"((a)[3]), \
                   "r"((b)[0]), "r"((b)[1]))

__device__ __forceinline__ uint32_t pack_bf2(__nv_bfloat16 a, __nv_bfloat16 b) {
    __nv_bfloat162 t; t.x = a; t.y = b;
    return *(uint32_t*)&t;
}

__device__ __forceinline__ int load_index(const void* p, long long i) {
    if (g_is64) return (int)((const long long*)p)[i];
    return ((const int*)p)[i];
}

// ---------------------------------------------------------------------------
// fused: dtype probe + zero deg + zero gsum/gcnt/cursor    (launch #1)
// ---------------------------------------------------------------------------
__global__ void detect_zero(const int* __restrict__ idx, int* deg,
                            float* gsum, float* gcnt, int N) {
    int i = blockIdx.x * blockDim.x + threadIdx.x;
    if (i < N) deg[i] = 0;
    if (blockIdx.x == 0) {
        if (threadIdx.x < 128) gsum[threadIdx.x] = 0.f;
        else if (threadIdx.x < 192) gcnt[threadIdx.x - 128] = 0.f;
        if (threadIdx.x == 0) {
            g_cursor = 0;
            int all0 = 1;
            #pragma unroll
            for (int k = 0; k < 64; k++)
                if (idx[2 * k + 1] != 0) all0 = 0;
            g_is64 = all0;
        }
    }
}

// ---------------------------------------------------------------------------
// weight prep: fragment-ordered B image                     (launch #2)
// ---------------------------------------------------------------------------
struct WPtrs { const float* w[4]; };
__global__ __launch_bounds__(256)
void prep_weight4(WPtrs ws, uint32_t* __restrict__ base) {
    const float* W = ws.w[blockIdx.y];
    uint32_t* dst = base + blockIdx.y * 8192;
    int ent = blockIdx.x * 256 + threadIdx.x;
    if (ent >= 8192) return;
    int q    = ent & 7;
    int lane = (ent >> 3) & 31;
    int s    = (ent >> 8) & 7;
    int wn   = (ent >> 11) & 3;
    int fp = q >> 2, j = q & 3;
    int n = wn * 32 + fp * 16 + ((j & 2) ? 8 : 0) + (lane >> 2);
    int k = s * 16 + ((j & 1) ? 8 : 0) + (lane & 3) * 2;
    float w0 = W[(size_t)k * 128 + n];
    float w1 = W[(size_t)(k + 1) * 128 + n];
    dst[ent] = pack_bf2(__float2bfloat16(w0), __float2bfloat16(w1));
}

// ---------------------------------------------------------------------------
// degree histogram                                         (launch #3)
// ---------------------------------------------------------------------------
__global__ void deg_kernel(const void* eidx, int* deg, int E) {
    int e = blockIdx.x * blockDim.x + threadIdx.x;
    if (e >= E) return;
    atomicAdd(&deg[load_index(eidx, (long long)E + e)], 1);
}

// ---------------------------------------------------------------------------
// shared GEMM core pieces
// ---------------------------------------------------------------------------
#define RSB 272
#define TILE_BYTES (128 * RSB)
#define SMEM_GEMM TILE_BYTES
#define GEMM_THREADS 512

// MMA mainloop + bf16 epilogue, A already staged in sA (bf16, RSB stride).
__device__ __forceinline__ void mma_core_epilogue(
    char* sA, const uint4* __restrict__ Bf,
    const float* __restrict__ bias, const int* __restrict__ deg,
    uint4* __restrict__ Yh, int M, int relu, int scaled,
    int row0, int tid, int wid, int lane) {

    const int warp_m = (wid & 3) * 32;
    const int wn8    = (wid >> 2) * 8;

    float acc[2][4][4];
    #pragma unroll
    for (int i = 0; i < 2; i++)
        #pragma unroll
        for (int j = 0; j < 4; j++)
            #pragma unroll
            for (int q = 0; q < 4; q++) acc[i][j][q] = 0.f;

    const uint32_t aA = smem_u32(sA);
    const int a_row  = lane & 15;
    const int a_koff = (lane & 16) ? 16 : 0;

    #pragma unroll
    for (int s = 0; s < 8; s++) {
        const int k0 = s * 16;
        uint32_t a[2][4];
        #pragma unroll
        for (int fm = 0; fm < 2; fm++) {
            uint32_t addr = aA + (warp_m + fm * 16 + a_row) * RSB
                          + k0 * 2 + a_koff;
            LDMATRIX_X4(a[fm][0], a[fm][1], a[fm][2], a[fm][3], addr);
        }
        const uint4* bp = Bf + (size_t)((wn8 + s) * 32 + lane) * 2;
        uint4 q0 = bp[0];
        uint4 q1 = bp[1];
        uint32_t b[4][2];
        b[0][0] = q0.x; b[0][1] = q0.y;
        b[1][0] = q0.z; b[1][1] = q0.w;
        b[2][0] = q1.x; b[2][1] = q1.y;
        b[3][0] = q1.z; b[3][1] = q1.w;
        #pragma unroll
        for (int fm = 0; fm < 2; fm++)
            #pragma unroll
            for (int fn = 0; fn < 4; fn++)
                MMA_BF16(acc[fm][fn], a[fm], b[fn]);
    }

    const int warp_n = (wid >> 2) * 32;
    const int erow = lane >> 2;
    const int ecol = (lane & 3) * 2;

    __syncthreads();   // done reading sA; reuse for staging
    #pragma unroll
    for (int fm = 0; fm < 2; fm++) {
        int r1 = warp_m + fm * 16 + erow;
        int r2 = r1 + 8;
        int g1 = row0 + r1, g2 = row0 + r2;
        float sc1 = 1.f, sc2 = 1.f;
        if (scaled) {
            sc1 = (g1 < M) ? rsqrtf((float)deg[g1] + 1.0f) : 0.f;
            sc2 = (g2 < M) ? rsqrtf((float)deg[g2] + 1.0f) : 0.f;
        }
        #pragma unroll
        for (int fn = 0; fn < 4; fn++) {
            int col = warp_n + fn * 8 + ecol;
            float b0 = bias ? bias[col]     : 0.f;
            float b1 = bias ? bias[col + 1] : 0.f;
            float2 v1, v2;
            v1.x = acc[fm][fn][0] + b0; v1.y = acc[fm][fn][1] + b1;
            v2.x = acc[fm][fn][2] + b0; v2.y = acc[fm][fn][3] + b1;
            if (relu) {
                v1.x = fmaxf(v1.x, 0.f); v1.y = fmaxf(v1.y, 0.f);
                v2.x = fmaxf(v2.x, 0.f); v2.y = fmaxf(v2.y, 0.f);
            }
            v1.x *= sc1; v1.y *= sc1;
            v2.x *= sc2; v2.y *= sc2;
            __nv_bfloat162 p1 = __float22bfloat162_rn(v1);
            __nv_bfloat162 p2 = __float22bfloat162_rn(v2);
            *(uint32_t*)(sA + r1 * RSB + col * 2) = *(uint32_t*)&p1;
            *(uint32_t*)(sA + r2 * RSB + col * 2) = *(uint32_t*)&p2;
        }
    }
    __syncthreads();
    #pragma unroll
    for (int i = tid; i < 2048; i += GEMM_THREADS) {
        int r = i >> 4, c = i & 15;
        int gr = row0 + r;
        if (gr < M)
            Yh[(size_t)gr * 16 + c] = *(uint4*)(sA + r * RSB + c * 16);
    }
}

// ---------------------------------------------------------------------------
// layer-1 GEMM: A from f32 X (converted)                    (launch #4)
// ---------------------------------------------------------------------------
__global__ __launch_bounds__(GEMM_THREADS, 2)
void gemm_mma(const float* __restrict__ Xf,
              const uint4* __restrict__ Bf,
              const int* __restrict__ deg,
              uint4* __restrict__ Yh, int M) {
    extern __shared__ __align__(16) char smem[];
    char* sA = smem;
    const int tid  = threadIdx.x;
    const int wid  = tid >> 5;
    const int lane = tid & 31;
    const int row0 = blockIdx.x * 128;

    #pragma unroll
    for (int it = 0; it < 8; it++) {
        int r  = wid + it * 16;
        int gr = row0 + r;
        float4 v = make_float4(0.f, 0.f, 0.f, 0.f);
        if (gr < M) v = *(const float4*)(Xf + (size_t)gr * CH + lane * 4);
        uint2 hh;
        hh.x = pack_bf2(__float2bfloat16(v.x), __float2bfloat16(v.y));
        hh.y = pack_bf2(__float2bfloat16(v.z), __float2bfloat16(v.w));
        *(uint2*)(sA + r * RSB + lane * 8) = hh;
    }
    __syncthreads();

    mma_core_epilogue(sA, Bf, nullptr, deg, Yh, M, 0, 1,
                      row0, tid, wid, lane);
}

// ---------------------------------------------------------------------------
// FUSED gather + GEMM:
//   A row r = bf16( relu( invs[r]*(Σ hb[nbr] + hb[r]) + gbias ) ), then
//   Y = A @ W (epilogue: scaled bf16 or bias+relu bf16).
// Gather: 4 passes x (16 warps x 2 nodes), half-warp per node, lane=uint4.
// ---------------------------------------------------------------------------
#define GACC(u) do { \
    float2 t0 = __bfloat1622float2(*(__nv_bfloat162*)&(u).x); \
    float2 t1 = __bfloat1622float2(*(__nv_bfloat162*)&(u).y); \
    float2 t2 = __bfloat1622float2(*(__nv_bfloat162*)&(u).z); \
    float2 t3 = __bfloat1622float2(*(__nv_bfloat162*)&(u).w); \
    a0 += t0.x; a1 += t0.y; a2 += t1.x; a3 += t1.y; \
    a4 += t2.x; a5 += t2.y; a6 += t3.x; a7 += t3.y; \
} while (0)

__global__ __launch_bounds__(GEMM_THREADS, 2)
void fused_gather_gemm(const uint4* __restrict__ hb,
                       const int* __restrict__ csr_start,
                       const int* __restrict__ deg,
                       const int* __restrict__ csr_src,
                       const float* __restrict__ invs,
                       const float* __restrict__ gbias,
                       const uint4* __restrict__ Bf,
                       const float* __restrict__ bias2,
                       uint4* __restrict__ Yh,
                       int M, int relu2, int scaled) {
    extern __shared__ __align__(16) char smem[];
    char* sA = smem;
    const int tid  = threadIdx.x;
    const int wid  = tid >> 5;
    const int lane = tid & 31;
    const int hl   = lane & 15;
    const int half = lane >> 4;
    const int row0 = blockIdx.x * 128;

    // --- gather phase: fill A tile (128 rows) ---
    float4 gb0 = *(const float4*)(gbias + hl * 8);
    float4 gb1 = *(const float4*)(gbias + hl * 8 + 4);
    const uint4* rowb = hb + hl;

    #pragma unroll
    for (int pass = 0; pass < 4; pass++) {
        int rloc = pass * 32 + wid * 2 + half;
        int node = row0 + rloc;
        float a0 = 0.f, a1 = 0.f, a2 = 0.f, a3 = 0.f;
        float a4 = 0.f, a5 = 0.f, a6 = 0.f, a7 = 0.f;
        if (node < M) {
            {
                uint4 u = rowb[(size_t)node * 16];
                GACC(u);
            }
            const int s0 = csr_start[node];
            const int e  = s0 + deg[node];
            int j = s0;
            for (; j + 4 <= e; j += 4) {
                int i0 = csr_src[j];
                int i1 = csr_src[j + 1];
                int i2 = csr_src[j + 2];
                int i3 = csr_src[j + 3];
                uint4 u0 = rowb[(size_t)i0 * 16];
                uint4 u1 = rowb[(size_t)i1 * 16];
                uint4 u2 = rowb[(size_t)i2 * 16];
                uint4 u3 = rowb[(size_t)i3 * 16];
                GACC(u0);
                GACC(u1);
                GACC(u2);
                GACC(u3);
            }
            for (; j < e; j++) {
                int i0 = csr_src[j];
                uint4 u0 = rowb[(size_t)i0 * 16];
                GACC(u0);
            }
            float invn = invs[node];
            a0 = fmaxf(fmaf(a0, invn, gb0.x), 0.f);
            a1 = fmaxf(fmaf(a1, invn, gb0.y), 0.f);
            a2 = fmaxf(fmaf(a2, invn, gb0.z), 0.f);
            a3 = fmaxf(fmaf(a3, invn, gb0.w), 0.f);
            a4 = fmaxf(fmaf(a4, invn, gb1.x), 0.f);
            a5 = fmaxf(fmaf(a5, invn, gb1.y), 0.f);
            a6 = fmaxf(fmaf(a6, invn, gb1.z), 0.f);
            a7 = fmaxf(fmaf(a7, invn, gb1.w), 0.f);
        }
        __nv_bfloat162 p0 = __float22bfloat162_rn(make_float2(a0, a1));
        __nv_bfloat162 p1 = __float22bfloat162_rn(make_float2(a2, a3));
        __nv_bfloat162 p2 = __float22bfloat162_rn(make_float2(a4, a5));
        __nv_bfloat162 p3 = __float22bfloat162_rn(make_float2(a6, a7));
        uint4 ov;
        ov.x = *(uint32_t*)&p0;
        ov.y = *(uint32_t*)&p1;
        ov.z = *(uint32_t*)&p2;
        ov.w = *(uint32_t*)&p3;
        *(uint4*)(sA + rloc * RSB + hl * 16) = ov;
    }
    __syncthreads();

    // --- MMA + epilogue (shared core) ---
    mma_core_epilogue(sA, Bf, bias2, deg, Yh, M, relu2, scaled,
                      row0, tid, wid, lane);
}

// ---------------------------------------------------------------------------
// one-pass scan (block scan + atomic base) + invs + cnt=0   (launch #5)
// ---------------------------------------------------------------------------
#define SCAN_B 512
__global__ __launch_bounds__(SCAN_B)
void scan_atomic(const int* __restrict__ deg, int* __restrict__ csr_start,
                 float* __restrict__ invs, int* __restrict__ cnt,
                 int* __restrict__ cursor, int N) {
    __shared__ int sh[SCAN_B];
    __shared__ int sbase;
    int tid = threadIdx.x;
    int gid = blockIdx.x * SCAN_B + tid;
    int v = (gid < N) ? deg[gid] : 0;
    if (gid < N) {
        invs[gid] = rsqrtf((float)v + 1.0f);
        cnt[gid] = 0;
    }
    sh[tid] = v;
    __syncthreads();
    #pragma unroll
    for (int off = 1; off < SCAN_B; off <<= 1) {
        int t = (tid >= off) ? sh[tid - off] : 0;
        __syncthreads();
        if (tid >= off) sh[tid] += t;
        __syncthreads();
    }
    if (tid == SCAN_B - 1) sbase = atomicAdd(cursor, sh[SCAN_B - 1]);
    __syncthreads();
    if (gid < N) csr_start[gid] = sbase + sh[tid] - v;
}

__global__ void fill_csr(const void* __restrict__ eidx,
                         const int* __restrict__ csr_start,
                         int* __restrict__ cnt,
                         int* __restrict__ csr_src, int E) {
    int e = blockIdx.x * blockDim.x + threadIdx.x;
    if (e >= E) return;
    int r = load_index(eidx, e);
    int c = load_index(eidx, (long long)E + e);
    int pos = csr_start[c] + atomicAdd(&cnt[c], 1);
    csr_src[pos] = r;
}

// ---------------------------------------------------------------------------
// fc2 (bf16 input) + per-graph pool
// ---------------------------------------------------------------------------
__global__ void fc2_pool(const __nv_bfloat16* __restrict__ h,
                         const void* __restrict__ batch,
                         const float* __restrict__ fcW2,
                         const float* __restrict__ fcb2,
                         float* __restrict__ gsum,
                         float* __restrict__ gcnt, int N) {
    int gw   = (blockIdx.x * blockDim.x + threadIdx.x) >> 5;
    int lane = threadIdx.x & 31;
    if (gw >= N) return;
    uint2 u = *(const uint2*)((const char*)h + (size_t)gw * 256 + lane * 8);
    float2 va = __bfloat1622float2(*(__nv_bfloat162*)&u.x);
    float2 vb = __bfloat1622float2(*(__nv_bfloat162*)&u.y);
    float4 w01 = *(const float4*)(fcW2 + 8 * lane);
    float4 w23 = *(const float4*)(fcW2 + 8 * lane + 4);
    float s0 = va.x * w01.x + va.y * w01.z + vb.x * w23.x + vb.y * w23.z;
    float s1 = va.x * w01.y + va.y * w01.w + vb.x * w23.y + vb.y * w23.w;
    #pragma unroll
    for (int o = 16; o > 0; o >>= 1) {
        s0 += __shfl_xor_sync(0xffffffffu, s0, o);
        s1 += __shfl_xor_sync(0xffffffffu, s1, o);
    }
    if (lane == 0) {
        int g = load_index(batch, gw);
        atomicAdd(&gsum[g * 2 + 0], s0 + fcb2[0]);
        atomicAdd(&gsum[g * 2 + 1], s1 + fcb2[1]);
        atomicAdd(&gcnt[g], 1.0f);
    }
}

__global__ void finalize(const float* gsum, const float* gcnt, float* out, int G) {
    int g = threadIdx.x;
    if (g >= G) return;
    float c  = fmaxf(gcnt[g], 1.0f);
    float p0 = gsum[g * 2 + 0] / c;
    float p1 = gsum[g * 2 + 1] / c;
    float m  = fmaxf(p0, p1);
    float e0 = expf(p0 - m);
    float e1 = expf(p1 - m);
    float inv = 1.0f / (e0 + e1);
    out[g * 2 + 0] = e0 * inv;
    out[g * 2 + 1] = e1 * inv;
}

// ---------------------------------------------------------------------------
// launch  (order: #4 = gemm_mma layer-1, the slot ncu profiles)
// ---------------------------------------------------------------------------
extern "C" void kernel_launch(void* const* d_in, const int* in_sizes, int n_in,
                              void* d_out, int out_size) {
    const float* x     = (const float*)d_in[0];
    const void*  eidx  = d_in[1];
    const void*  batch = d_in[2];
    const float* W1    = (const float*)d_in[3];
    const float* b1    = (const float*)d_in[4];
    const float* W2    = (const float*)d_in[5];
    const float* b2    = (const float*)d_in[6];
    const float* W3    = (const float*)d_in[7];
    const float* b3    = (const float*)d_in[8];
    const float* fcW1  = (const float*)d_in[9];
    const float* fcb1  = (const float*)d_in[10];
    const float* fcW2  = (const float*)d_in[11];
    const float* fcb2  = (const float*)d_in[12];

    const int N = in_sizes[0] / CH;
    const int E = in_sizes[1] / 2;
    const int G = out_size / 2;
    float* out = (float*)d_out;

    float *invs, *gsum, *gcnt;
    __nv_bfloat16 *bufAh, *bufBh;
    int *deg, *cnt, *csr_start, *csr_src, *cursor;
    uint32_t* wprep;
    cudaGetSymbolAddress((void**)&bufAh,     g_bufAh);
    cudaGetSymbolAddress((void**)&bufBh,     g_bufBh);
    cudaGetSymbolAddress((void**)&invs,      g_invs);
    cudaGetSymbolAddress((void**)&gsum,      g_gsum);
    cudaGetSymbolAddress((void**)&gcnt,      g_gcnt);
    cudaGetSymbolAddress((void**)&deg,       g_deg);
    cudaGetSymbolAddress((void**)&cnt,       g_cnt);
    cudaGetSymbolAddress((void**)&csr_start, g_csr_start);
    cudaGetSymbolAddress((void**)&csr_src,   g_csr_src);
    cudaGetSymbolAddress((void**)&cursor,    g_cursor);
    cudaGetSymbolAddress((void**)&wprep,     g_wprep);

    cudaFuncSetAttribute(gemm_mma, cudaFuncAttributeMaxDynamicSharedMemorySize,
                         SMEM_GEMM);
    cudaFuncSetAttribute(fused_gather_gemm,
                         cudaFuncAttributeMaxDynamicSharedMemorySize, SMEM_GEMM);

    const int nb = (N + SCAN_B - 1) / SCAN_B;
    const int gemm_blocks = (N + 127) / 128;

    WPtrs wp;
    wp.w[0] = W1; wp.w[1] = W2; wp.w[2] = W3; wp.w[3] = fcW1;

    detect_zero<<<(N + 255) / 256, 256>>>((const int*)eidx, deg, gsum, gcnt, N); // 1
    prep_weight4<<<dim3(32, 4), 256>>>(wp, wprep);                               // 2
    deg_kernel<<<(E + 255) / 256, 256>>>(eidx, deg, E);                          // 3

    // #4: layer-1 GEMM  x@W1 -> bufBh (scaled bf16)
    gemm_mma<<<gemm_blocks, GEMM_THREADS, SMEM_GEMM>>>(x, (const uint4*)wprep,
                                                       deg, (uint4*)bufBh, N);   // 4

    // CSR build
    scan_atomic<<<nb, SCAN_B>>>(deg, csr_start, invs, cnt, cursor, N);           // 5
    fill_csr<<<(E + 255) / 256, 256>>>(eidx, csr_start, cnt, csr_src, E);        // 6

    // fused layer 2: gather(bufBh, b1) @ W2 -> bufAh (scaled)
    fused_gather_gemm<<<gemm_blocks, GEMM_THREADS, SMEM_GEMM>>>(
        (const uint4*)bufBh, csr_start, deg, csr_src, invs, b1,
        (const uint4*)(wprep + 8192), nullptr, (uint4*)bufAh, N, 0, 1);          // 7

    // fused layer 3: gather(bufAh, b2) @ W3 -> bufBh (scaled)
    fused_gather_gemm<<<gemm_blocks, GEMM_THREADS, SMEM_GEMM>>>(
        (const uint4*)bufAh, csr_start, deg, csr_src, invs, b2,
        (const uint4*)(wprep + 2 * 8192), nullptr, (uint4*)bufBh, N, 0, 1);      // 8

    // fused fc1: gather(bufBh, b3) @ fcW1 + fcb1, relu -> bufAh (unscaled)
    fused_gather_gemm<<<gemm_blocks, GEMM_THREADS, SMEM_GEMM>>>(
        (const uint4*)bufBh, csr_start, deg, csr_src, invs, b3,
        (const uint4*)(wprep + 3 * 8192), fcb1, (uint4*)bufAh, N, 1, 0);         // 9

    fc2_pool<<<(N + 7) / 8, 256>>>(bufAh, batch, fcW2, fcb2, gsum, gcnt, N);
    finalize<<<1, (G + 31) / 32 * 32>>>(gsum, gcnt, out, G);
}

// round 16
// speedup vs baseline: 1.0322x; 1.0322x over previous
#include <cuda_runtime.h>
#include <cuda_bf16.h>
#include <cstdint>
#include <cstddef>

#define MAXN 50000
#define MAXE 800000
#define CH   128

// ---------------------------------------------------------------------------
// Scratch (device globals)
// ---------------------------------------------------------------------------
__device__ int   g_is64;
__device__ int   g_cursor;
__device__ int   g_deg [MAXN];
__device__ int   g_cnt [MAXN];
__device__ int   g_csr_start[MAXN + 1];
__device__ int   g_csr_src[MAXE];
__device__ float g_invs[MAXN];
__device__ __nv_bfloat16 g_bufAh[(size_t)MAXN * CH];   // bf16 inter-layer h
__device__ __nv_bfloat16 g_bufBh[(size_t)MAXN * CH];   // bf16 GEMM out
__device__ float g_gsum[128];
__device__ float g_gcnt[64];
__device__ uint32_t g_wprep[4][8192];                  // fragment-ordered B images

// ---------------------------------------------------------------------------
// helpers
// ---------------------------------------------------------------------------
__device__ __forceinline__ uint32_t smem_u32(const void* p) {
    uint32_t a;
    asm("{ .reg .u64 t; cvta.to.shared.u64 t, %1; cvt.u32.u64 %0, t; }"
        : "=r"(a) : "l"(p));
    return a;
}

#define LDMATRIX_X4(r0, r1, r2, r3, addr) \
    asm volatile("ldmatrix.sync.aligned.m8n8.x4.shared.b16 {%0,%1,%2,%3}, [%4];" \
                 : "=r"(r0), "=r"(r1), "=r"(r2), "=r"(r3) : "r"(addr))

#define MMA_BF16(d, a, b) \
    asm volatile("mma.sync.aligned.m16n8k16.row.col.f32.bf16.bf16.f32 " \
                 "{%0,%1,%2,%3}, {%4,%5,%6,%7}, {%8,%9}, {%0,%1,%2,%3};" \
                 : "+f"((d)[0]), "+f"((d)[1]), "+f"((d)[2]), "+f"((d)[3]) \
                 : "r"((a)[0]), "r"((a)[1]), "r"((a)[2]), "r"((a)[3]), \
                   "r"((b)[0]), "r"((b)[1]))

__device__ __forceinline__ uint32_t pack_bf2(__nv_bfloat16 a, __nv_bfloat16 b) {
    __nv_bfloat162 t; t.x = a; t.y = b;
    return *(uint32_t*)&t;
}

__device__ __forceinline__ int load_index(const void* p, long long i) {
    if (g_is64) return (int)((const long long*)p)[i];
    return ((const int*)p)[i];
}

// ---------------------------------------------------------------------------
// fused: dtype probe + zero deg + zero gsum/gcnt/cursor    (launch #1)
// ---------------------------------------------------------------------------
__global__ void detect_zero(const int* __restrict__ idx, int* deg,
                            float* gsum, float* gcnt, int N) {
    int i = blockIdx.x * blockDim.x + threadIdx.x;
    if (i < N) deg[i] = 0;
    if (blockIdx.x == 0) {
        if (threadIdx.x < 128) gsum[threadIdx.x] = 0.f;
        else if (threadIdx.x < 192) gcnt[threadIdx.x - 128] = 0.f;
        if (threadIdx.x == 0) {
            g_cursor = 0;
            int all0 = 1;
            #pragma unroll
            for (int k = 0; k < 64; k++)
                if (idx[2 * k + 1] != 0) all0 = 0;
            g_is64 = all0;
        }
    }
}

// ---------------------------------------------------------------------------
// weight prep: fragment-ordered B image                     (launch #2)
// ---------------------------------------------------------------------------
struct WPtrs { const float* w[4]; };
__global__ __launch_bounds__(256)
void prep_weight4(WPtrs ws, uint32_t* __restrict__ base) {
    const float* W = ws.w[blockIdx.y];
    uint32_t* dst = base + blockIdx.y * 8192;
    int ent = blockIdx.x * 256 + threadIdx.x;
    if (ent >= 8192) return;
    int q    = ent & 7;
    int lane = (ent >> 3) & 31;
    int s    = (ent >> 8) & 7;
    int wn   = (ent >> 11) & 3;
    int fp = q >> 2, j = q & 3;
    int n = wn * 32 + fp * 16 + ((j & 2) ? 8 : 0) + (lane >> 2);
    int k = s * 16 + ((j & 1) ? 8 : 0) + (lane & 3) * 2;
    float w0 = W[(size_t)k * 128 + n];
    float w1 = W[(size_t)(k + 1) * 128 + n];
    dst[ent] = pack_bf2(__float2bfloat16(w0), __float2bfloat16(w1));
}

// ---------------------------------------------------------------------------
// degree histogram                                         (launch #3)
// ---------------------------------------------------------------------------
__global__ void deg_kernel(const void* eidx, int* deg, int E) {
    int e = blockIdx.x * blockDim.x + threadIdx.x;
    if (e >= E) return;
    atomicAdd(&deg[load_index(eidx, (long long)E + e)], 1);
}

// ---------------------------------------------------------------------------
// tensor-core GEMM: A via smem/ldmatrix, B fragments from global.
// Output: bf16 image (staged through smem); scaled (GCN) or bias+relu (fc1).
// ---------------------------------------------------------------------------
#define RSB 272
#define TILE_BYTES (128 * RSB)
#define SMEM_GEMM TILE_BYTES
#define GEMM_THREADS 512

__global__ __launch_bounds__(GEMM_THREADS, 2)
void gemm_mma(const float* __restrict__ Xf,
              const __nv_bfloat16* __restrict__ Xh,
              const uint4* __restrict__ Bf,
              const float* __restrict__ bias, const int* __restrict__ deg,
              uint4* __restrict__ Yh, int M, int relu, int scaled) {
    extern __shared__ __align__(16) char smem[];
    char* sA = smem;

    const int tid  = threadIdx.x;
    const int wid  = tid >> 5;
    const int lane = tid & 31;
    const int row0 = blockIdx.x * 128;

    if (Xh) {
        #pragma unroll
        for (int i = tid; i < 2048; i += GEMM_THREADS) {
            int r = i >> 4, c = i & 15;
            int gr = row0 + r;
            float4 v = make_float4(0.f, 0.f, 0.f, 0.f);
            if (gr < M)
                v = *(const float4*)((const char*)Xh + (size_t)gr * 256 + c * 16);
            *(float4*)(sA + r * RSB + c * 16) = v;
        }
    } else {
        #pragma unroll
        for (int it = 0; it < 8; it++) {
            int r  = wid + it * 16;
            int gr = row0 + r;
            float4 v = make_float4(0.f, 0.f, 0.f, 0.f);
            if (gr < M) v = *(const float4*)(Xf + (size_t)gr * CH + lane * 4);
            uint2 hh;
            hh.x = pack_bf2(__float2bfloat16(v.x), __float2bfloat16(v.y));
            hh.y = pack_bf2(__float2bfloat16(v.z), __float2bfloat16(v.w));
            *(uint2*)(sA + r * RSB + lane * 8) = hh;
        }
    }
    __syncthreads();

    const int warp_m = (wid & 3) * 32;
    const int wn8    = (wid >> 2) * 8;

    float acc[2][4][4];
    #pragma unroll
    for (int i = 0; i < 2; i++)
        #pragma unroll
        for (int j = 0; j < 4; j++)
            #pragma unroll
            for (int q = 0; q < 4; q++) acc[i][j][q] = 0.f;

    const uint32_t aA = smem_u32(sA);
    const int a_row  = lane & 15;
    const int a_koff = (lane & 16) ? 16 : 0;

    #pragma unroll
    for (int s = 0; s < 8; s++) {
        const int k0 = s * 16;
        uint32_t a[2][4];
        #pragma unroll
        for (int fm = 0; fm < 2; fm++) {
            uint32_t addr = aA + (warp_m + fm * 16 + a_row) * RSB
                          + k0 * 2 + a_koff;
            LDMATRIX_X4(a[fm][0], a[fm][1], a[fm][2], a[fm][3], addr);
        }
        const uint4* bp = Bf + (size_t)((wn8 + s) * 32 + lane) * 2;
        uint4 q0 = bp[0];
        uint4 q1 = bp[1];
        uint32_t b[4][2];
        b[0][0] = q0.x; b[0][1] = q0.y;
        b[1][0] = q0.z; b[1][1] = q0.w;
        b[2][0] = q1.x; b[2][1] = q1.y;
        b[3][0] = q1.z; b[3][1] = q1.w;
        #pragma unroll
        for (int fm = 0; fm < 2; fm++)
            #pragma unroll
            for (int fn = 0; fn < 4; fn++)
                MMA_BF16(acc[fm][fn], a[fm], b[fn]);
    }

    const int warp_n = (wid >> 2) * 32;
    const int erow = lane >> 2;
    const int ecol = (lane & 3) * 2;

    __syncthreads();
    #pragma unroll
    for (int fm = 0; fm < 2; fm++) {
        int r1 = warp_m + fm * 16 + erow;
        int r2 = r1 + 8;
        int g1 = row0 + r1, g2 = row0 + r2;
        float sc1 = 1.f, sc2 = 1.f;
        if (scaled) {
            sc1 = (g1 < M) ? rsqrtf((float)deg[g1] + 1.0f) : 0.f;
            sc2 = (g2 < M) ? rsqrtf((float)deg[g2] + 1.0f) : 0.f;
        }
        #pragma unroll
        for (int fn = 0; fn < 4; fn++) {
            int col = warp_n + fn * 8 + ecol;
            float b0 = bias ? bias[col]     : 0.f;
            float b1 = bias ? bias[col + 1] : 0.f;
            float2 v1, v2;
            v1.x = acc[fm][fn][0] + b0; v1.y = acc[fm][fn][1] + b1;
            v2.x = acc[fm][fn][2] + b0; v2.y = acc[fm][fn][3] + b1;
            if (relu) {
                v1.x = fmaxf(v1.x, 0.f); v1.y = fmaxf(v1.y, 0.f);
                v2.x = fmaxf(v2.x, 0.f); v2.y = fmaxf(v2.y, 0.f);
            }
            v1.x *= sc1; v1.y *= sc1;
            v2.x *= sc2; v2.y *= sc2;
            __nv_bfloat162 p1 = __float22bfloat162_rn(v1);
            __nv_bfloat162 p2 = __float22bfloat162_rn(v2);
            *(uint32_t*)(sA + r1 * RSB + col * 2) = *(uint32_t*)&p1;
            *(uint32_t*)(sA + r2 * RSB + col * 2) = *(uint32_t*)&p2;
        }
    }
    __syncthreads();
    #pragma unroll
    for (int i = tid; i < 2048; i += GEMM_THREADS) {
        int r = i >> 4, c = i & 15;
        int gr = row0 + r;
        if (gr < M)
            Yh[(size_t)gr * 16 + c] = *(uint4*)(sA + r * RSB + c * 16);
    }
}

// ---------------------------------------------------------------------------
// one-pass scan (block scan + atomic base) + invs + cnt=0   (launch #5)
// ---------------------------------------------------------------------------
#define SCAN_B 512
__global__ __launch_bounds__(SCAN_B)
void scan_atomic(const int* __restrict__ deg, int* __restrict__ csr_start,
                 float* __restrict__ invs, int* __restrict__ cnt,
                 int* __restrict__ cursor, int N) {
    __shared__ int sh[SCAN_B];
    __shared__ int sbase;
    int tid = threadIdx.x;
    int gid = blockIdx.x * SCAN_B + tid;
    int v = (gid < N) ? deg[gid] : 0;
    if (gid < N) {
        invs[gid] = rsqrtf((float)v + 1.0f);
        cnt[gid] = 0;
    }
    sh[tid] = v;
    __syncthreads();
    #pragma unroll
    for (int off = 1; off < SCAN_B; off <<= 1) {
        int t = (tid >= off) ? sh[tid - off] : 0;
        __syncthreads();
        if (tid >= off) sh[tid] += t;
        __syncthreads();
    }
    if (tid == SCAN_B - 1) sbase = atomicAdd(cursor, sh[SCAN_B - 1]);
    __syncthreads();
    if (gid < N) csr_start[gid] = sbase + sh[tid] - v;
}

__global__ void fill_csr(const void* __restrict__ eidx,
                         const int* __restrict__ csr_start,
                         int* __restrict__ cnt,
                         int* __restrict__ csr_src, int E) {
    int e = blockIdx.x * blockDim.x + threadIdx.x;
    if (e >= E) return;
    int r = load_index(eidx, e);
    int c = load_index(eidx, (long long)E + e);
    int pos = csr_start[c] + atomicAdd(&cnt[c], 1);
    csr_src[pos] = r;
}

// ---------------------------------------------------------------------------
// CSR gather: ONE warp per node; the two half-warps split the edge list
// (even/odd neighbors), each accumulating the full row (16 lanes x uint4).
// Partials merged via shfl_xor(16). Trip count = ceil(deg/2).
// ---------------------------------------------------------------------------
#define GACC(u) do { \
    float2 t0 = __bfloat1622float2(*(__nv_bfloat162*)&(u).x); \
    float2 t1 = __bfloat1622float2(*(__nv_bfloat162*)&(u).y); \
    float2 t2 = __bfloat1622float2(*(__nv_bfloat162*)&(u).z); \
    float2 t3 = __bfloat1622float2(*(__nv_bfloat162*)&(u).w); \
    a0 += t0.x; a1 += t0.y; a2 += t1.x; a3 += t1.y; \
    a4 += t2.x; a5 += t2.y; a6 += t3.x; a7 += t3.y; \
} while (0)

__global__ __launch_bounds__(256)
void gather_combine(const int* __restrict__ csr_start,
                    const int* __restrict__ deg,
                    const int* __restrict__ csr_src,
                    const uint4* __restrict__ hb,
                    const float* __restrict__ invs,
                    const float* __restrict__ bias,
                    uint4* __restrict__ outh, int N) {
    int node = (blockIdx.x * blockDim.x + threadIdx.x) >> 5;
    int lane = threadIdx.x & 31;
    int hl   = lane & 15;
    int half = lane >> 4;
    if (node >= N) return;

    const int s0 = csr_start[node];
    const int e  = s0 + deg[node];
    const uint4* rowb = hb + hl;

    float a0 = 0.f, a1 = 0.f, a2 = 0.f, a3 = 0.f;
    float a4 = 0.f, a5 = 0.f, a6 = 0.f, a7 = 0.f;
    if (half == 0) {
        uint4 u = rowb[(size_t)node * 16];
        GACC(u);                       // self term on half 0 only
    }

    // half h takes neighbors s0+h, s0+h+2, ... ; 2-deep unroll per half.
    int j = s0 + half;
    for (; j + 2 < e; j += 4) {
        int i0 = csr_src[j];
        int i1 = csr_src[j + 2];
        uint4 u0 = rowb[(size_t)i0 * 16];
        uint4 u1 = rowb[(size_t)i1 * 16];
        GACC(u0);
        GACC(u1);
    }
    if (j < e) {
        int i0 = csr_src[j];
        uint4 u0 = rowb[(size_t)i0 * 16];
        GACC(u0);
    }

    // merge the two half-warp partials
    a0 += __shfl_xor_sync(0xffffffffu, a0, 16);
    a1 += __shfl_xor_sync(0xffffffffu, a1, 16);
    a2 += __shfl_xor_sync(0xffffffffu, a2, 16);
    a3 += __shfl_xor_sync(0xffffffffu, a3, 16);
    a4 += __shfl_xor_sync(0xffffffffu, a4, 16);
    a5 += __shfl_xor_sync(0xffffffffu, a5, 16);
    a6 += __shfl_xor_sync(0xffffffffu, a6, 16);
    a7 += __shfl_xor_sync(0xffffffffu, a7, 16);

    if (half == 0) {
        float invn = invs[node];
        float4 b0 = *(const float4*)(bias + hl * 8);
        float4 b1 = *(const float4*)(bias + hl * 8 + 4);
        float2 o01, o23, o45, o67;
        o01.x = fmaxf(fmaf(a0, invn, b0.x), 0.f);
        o01.y = fmaxf(fmaf(a1, invn, b0.y), 0.f);
        o23.x = fmaxf(fmaf(a2, invn, b0.z), 0.f);
        o23.y = fmaxf(fmaf(a3, invn, b0.w), 0.f);
        o45.x = fmaxf(fmaf(a4, invn, b1.x), 0.f);
        o45.y = fmaxf(fmaf(a5, invn, b1.y), 0.f);
        o67.x = fmaxf(fmaf(a6, invn, b1.z), 0.f);
        o67.y = fmaxf(fmaf(a7, invn, b1.w), 0.f);
        __nv_bfloat162 p0 = __float22bfloat162_rn(o01);
        __nv_bfloat162 p1 = __float22bfloat162_rn(o23);
        __nv_bfloat162 p2 = __float22bfloat162_rn(o45);
        __nv_bfloat162 p3 = __float22bfloat162_rn(o67);
        uint4 ov;
        ov.x = *(uint32_t*)&p0;
        ov.y = *(uint32_t*)&p1;
        ov.z = *(uint32_t*)&p2;
        ov.w = *(uint32_t*)&p3;
        outh[(size_t)node * 16 + hl] = ov;
    }
}

// ---------------------------------------------------------------------------
// fc2 (bf16 input) + per-graph pool
// ---------------------------------------------------------------------------
__global__ void fc2_pool(const __nv_bfloat16* __restrict__ h,
                         const void* __restrict__ batch,
                         const float* __restrict__ fcW2,
                         const float* __restrict__ fcb2,
                         float* __restrict__ gsum,
                         float* __restrict__ gcnt, int N) {
    int gw   = (blockIdx.x * blockDim.x + threadIdx.x) >> 5;
    int lane = threadIdx.x & 31;
    if (gw >= N) return;
    uint2 u = *(const uint2*)((const char*)h + (size_t)gw * 256 + lane * 8);
    float2 va = __bfloat1622float2(*(__nv_bfloat162*)&u.x);
    float2 vb = __bfloat1622float2(*(__nv_bfloat162*)&u.y);
    float4 w01 = *(const float4*)(fcW2 + 8 * lane);
    float4 w23 = *(const float4*)(fcW2 + 8 * lane + 4);
    float s0 = va.x * w01.x + va.y * w01.z + vb.x * w23.x + vb.y * w23.z;
    float s1 = va.x * w01.y + va.y * w01.w + vb.x * w23.y + vb.y * w23.w;
    #pragma unroll
    for (int o = 16; o > 0; o >>= 1) {
        s0 += __shfl_xor_sync(0xffffffffu, s0, o);
        s1 += __shfl_xor_sync(0xffffffffu, s1, o);
    }
    if (lane == 0) {
        int g = load_index(batch, gw);
        atomicAdd(&gsum[g * 2 + 0], s0 + fcb2[0]);
        atomicAdd(&gsum[g * 2 + 1], s1 + fcb2[1]);
        atomicAdd(&gcnt[g], 1.0f);
    }
}

__global__ void finalize(const float* gsum, const float* gcnt, float* out, int G) {
    int g = threadIdx.x;
    if (g >= G) return;
    float c  = fmaxf(gcnt[g], 1.0f);
    float p0 = gsum[g * 2 + 0] / c;
    float p1 = gsum[g * 2 + 1] / c;
    float m  = fmaxf(p0, p1);
    float e0 = expf(p0 - m);
    float e1 = expf(p1 - m);
    float inv = 1.0f / (e0 + e1);
    out[g * 2 + 0] = e0 * inv;
    out[g * 2 + 1] = e1 * inv;
}

// ---------------------------------------------------------------------------
// launch  (order: #4 = gemm_mma layer-1, the slot ncu profiles)
// ---------------------------------------------------------------------------
extern "C" void kernel_launch(void* const* d_in, const int* in_sizes, int n_in,
                              void* d_out, int out_size) {
    const float* x     = (const float*)d_in[0];
    const void*  eidx  = d_in[1];
    const void*  batch = d_in[2];
    const float* W1    = (const float*)d_in[3];
    const float* b1    = (const float*)d_in[4];
    const float* W2    = (const float*)d_in[5];
    const float* b2    = (const float*)d_in[6];
    const float* W3    = (const float*)d_in[7];
    const float* b3    = (const float*)d_in[8];
    const float* fcW1  = (const float*)d_in[9];
    const float* fcb1  = (const float*)d_in[10];
    const float* fcW2  = (const float*)d_in[11];
    const float* fcb2  = (const float*)d_in[12];

    const int N = in_sizes[0] / CH;
    const int E = in_sizes[1] / 2;
    const int G = out_size / 2;
    float* out = (float*)d_out;

    float *invs, *gsum, *gcnt;
    __nv_bfloat16 *bufAh, *bufBh;
    int *deg, *cnt, *csr_start, *csr_src, *cursor;
    uint32_t* wprep;
    cudaGetSymbolAddress((void**)&bufAh,     g_bufAh);
    cudaGetSymbolAddress((void**)&bufBh,     g_bufBh);
    cudaGetSymbolAddress((void**)&invs,      g_invs);
    cudaGetSymbolAddress((void**)&gsum,      g_gsum);
    cudaGetSymbolAddress((void**)&gcnt,      g_gcnt);
    cudaGetSymbolAddress((void**)&deg,       g_deg);
    cudaGetSymbolAddress((void**)&cnt,       g_cnt);
    cudaGetSymbolAddress((void**)&csr_start, g_csr_start);
    cudaGetSymbolAddress((void**)&csr_src,   g_csr_src);
    cudaGetSymbolAddress((void**)&cursor,    g_cursor);
    cudaGetSymbolAddress((void**)&wprep,     g_wprep);

    cudaFuncSetAttribute(gemm_mma, cudaFuncAttributeMaxDynamicSharedMemorySize,
                         SMEM_GEMM);

    const int nb = (N + SCAN_B - 1) / SCAN_B;
    const int gemm_blocks = (N + 127) / 128;
    const int gather_blocks = (N + 7) / 8;   // 1 node/warp, 8 warps/block

    WPtrs wp;
    wp.w[0] = W1; wp.w[1] = W2; wp.w[2] = W3; wp.w[3] = fcW1;

    detect_zero<<<(N + 255) / 256, 256>>>((const int*)eidx, deg, gsum, gcnt, N); // 1
    prep_weight4<<<dim3(32, 4), 256>>>(wp, wprep);                               // 2
    deg_kernel<<<(E + 255) / 256, 256>>>(eidx, deg, E);                          // 3

    // #4: layer-1 GEMM (f32 A path, scaled bf16 out)
    gemm_mma<<<gemm_blocks, GEMM_THREADS, SMEM_GEMM>>>(x, nullptr,
                                                       (const uint4*)wprep,
                                                       nullptr, deg,
                                                       (uint4*)bufBh, N, 0, 1);  // 4

    // CSR build
    scan_atomic<<<nb, SCAN_B>>>(deg, csr_start, invs, cnt, cursor, N);           // 5
    fill_csr<<<(E + 255) / 256, 256>>>(eidx, csr_start, cnt, csr_src, E);        // 6

    // layer 1 gather
    gather_combine<<<gather_blocks, 256>>>(csr_start, deg, csr_src,
                                           (const uint4*)bufBh, invs, b1,
                                           (uint4*)bufAh, N);                    // 7
    // layers 2..3
    const float* bs23[2] = { b2, b3 };
    const uint32_t* wp23[2] = { wprep + 8192, wprep + 2 * 8192 };
    for (int l = 0; l < 2; l++) {
        gemm_mma<<<gemm_blocks, GEMM_THREADS, SMEM_GEMM>>>(nullptr, bufAh,
                                                           (const uint4*)wp23[l],
                                                           nullptr, deg,
                                                           (uint4*)bufBh, N, 0, 1);
        gather_combine<<<gather_blocks, 256>>>(csr_start, deg, csr_src,
                                               (const uint4*)bufBh, invs, bs23[l],
                                               (uint4*)bufAh, N);
    }

    // fc1: bf16 in, bias+relu, bf16 out (no degree scale)
    gemm_mma<<<gemm_blocks, GEMM_THREADS, SMEM_GEMM>>>(nullptr, bufAh,
                                                       (const uint4*)(wprep + 3 * 8192),
                                                       fcb1, deg,
                                                       (uint4*)bufBh, N, 1, 0);

    fc2_pool<<<(N + 7) / 8, 256>>>(bufBh, batch, fcW2, fcb2, gsum, gcnt, N);
    finalize<<<1, (G + 31) / 32 * 32>>>(gsum, gcnt, out, G);
}

// round 17
// speedup vs baseline: 1.0730x; 1.0395x over previous
#include <cuda_runtime.h>
#include <cuda_bf16.h>
#include <cstdint>
#include <cstddef>

#define MAXN 50000
#define MAXE 800000
#define CH   128

// ---------------------------------------------------------------------------
// Scratch (device globals)
// ---------------------------------------------------------------------------
__device__ int   g_is64;
__device__ int   g_cursor;
__device__ int   g_deg [MAXN];
__device__ int   g_cnt [MAXN];
__device__ int   g_csr_start[MAXN + 1];
__device__ int   g_csr_src[MAXE];
__device__ float g_invs[MAXN];
__device__ __nv_bfloat16 g_bufAh[(size_t)MAXN * CH];   // bf16 inter-layer h
__device__ __nv_bfloat16 g_bufBh[(size_t)MAXN * CH];   // bf16 GEMM out
__device__ float g_gsum[128];
__device__ float g_gcnt[64];
__device__ uint32_t g_wprep[4][8192];                  // fragment-ordered B images

// ---------------------------------------------------------------------------
// helpers
// ---------------------------------------------------------------------------
__device__ __forceinline__ uint32_t smem_u32(const void* p) {
    uint32_t a;
    asm("{ .reg .u64 t; cvta.to.shared.u64 t, %1; cvt.u32.u64 %0, t; }"
        : "=r"(a) : "l"(p));
    return a;
}

#define LDMATRIX_X4(r0, r1, r2, r3, addr) \
    asm volatile("ldmatrix.sync.aligned.m8n8.x4.shared.b16 {%0,%1,%2,%3}, [%4];" \
                 : "=r"(r0), "=r"(r1), "=r"(r2), "=r"(r3) : "r"(addr))

#define MMA_BF16(d, a, b) \
    asm volatile("mma.sync.aligned.m16n8k16.row.col.f32.bf16.bf16.f32 " \
                 "{%0,%1,%2,%3}, {%4,%5,%6,%7}, {%8,%9}, {%0,%1,%2,%3};" \
                 : "+f"((d)[0]), "+f"((d)[1]), "+f"((d)[2]), "+f"((d)[3]) \
                 : "r"((a)[0]), "r"((a)[1]), "r"((a)[2]), "r"((a)[3]), \
                   "r"((b)[0]), "r"((b)[1]))

__device__ __forceinline__ uint32_t pack_bf2(__nv_bfloat16 a, __nv_bfloat16 b) {
    __nv_bfloat162 t; t.x = a; t.y = b;
    return *(uint32_t*)&t;
}

__device__ __forceinline__ int load_index(const void* p, long long i) {
    if (g_is64) return (int)((const long long*)p)[i];
    return ((const int*)p)[i];
}

// ---------------------------------------------------------------------------
// fused: dtype probe + zero deg + zero gsum/gcnt/cursor    (launch #1)
// ---------------------------------------------------------------------------
__global__ void detect_zero(const int* __restrict__ idx, int* deg,
                            float* gsum, float* gcnt, int N) {
    int i = blockIdx.x * blockDim.x + threadIdx.x;
    if (i < N) deg[i] = 0;
    if (blockIdx.x == 0) {
        if (threadIdx.x < 128) gsum[threadIdx.x] = 0.f;
        else if (threadIdx.x < 192) gcnt[threadIdx.x - 128] = 0.f;
        if (threadIdx.x == 0) {
            g_cursor = 0;
            int all0 = 1;
            #pragma unroll
            for (int k = 0; k < 64; k++)
                if (idx[2 * k + 1] != 0) all0 = 0;
            g_is64 = all0;
        }
    }
}

// ---------------------------------------------------------------------------
// weight prep: fragment-ordered B image                     (launch #2)
// ---------------------------------------------------------------------------
struct WPtrs { const float* w[4]; };
__global__ __launch_bounds__(256)
void prep_weight4(WPtrs ws, uint32_t* __restrict__ base) {
    const float* W = ws.w[blockIdx.y];
    uint32_t* dst = base + blockIdx.y * 8192;
    int ent = blockIdx.x * 256 + threadIdx.x;
    if (ent >= 8192) return;
    int q    = ent & 7;
    int lane = (ent >> 3) & 31;
    int s    = (ent >> 8) & 7;
    int wn   = (ent >> 11) & 3;
    int fp = q >> 2, j = q & 3;
    int n = wn * 32 + fp * 16 + ((j & 2) ? 8 : 0) + (lane >> 2);
    int k = s * 16 + ((j & 1) ? 8 : 0) + (lane & 3) * 2;
    float w0 = W[(size_t)k * 128 + n];
    float w1 = W[(size_t)(k + 1) * 128 + n];
    dst[ent] = pack_bf2(__float2bfloat16(w0), __float2bfloat16(w1));
}

// ---------------------------------------------------------------------------
// degree histogram                                         (launch #3)
// ---------------------------------------------------------------------------
__global__ void deg_kernel(const void* eidx, int* deg, int E) {
    int e = blockIdx.x * blockDim.x + threadIdx.x;
    if (e >= E) return;
    atomicAdd(&deg[load_index(eidx, (long long)E + e)], 1);
}

// ---------------------------------------------------------------------------
// tensor-core GEMM: A via smem/ldmatrix, B fragments from global.
// Per k-step: B LDGs issued FIRST so their L2 latency overlaps the A
// ldmatrix. Output: bf16 image (scaled for GCN, bias+relu for fc1).
// ---------------------------------------------------------------------------
#define RSB 272
#define TILE_BYTES (128 * RSB)
#define SMEM_GEMM TILE_BYTES
#define GEMM_THREADS 512

__global__ __launch_bounds__(GEMM_THREADS, 2)
void gemm_mma(const float* __restrict__ Xf,
              const __nv_bfloat16* __restrict__ Xh,
              const uint4* __restrict__ Bf,
              const float* __restrict__ bias, const int* __restrict__ deg,
              uint4* __restrict__ Yh, int M, int relu, int scaled) {
    extern __shared__ __align__(16) char smem[];
    char* sA = smem;

    const int tid  = threadIdx.x;
    const int wid  = tid >> 5;
    const int lane = tid & 31;
    const int row0 = blockIdx.x * 128;

    if (Xh) {
        #pragma unroll
        for (int i = tid; i < 2048; i += GEMM_THREADS) {
            int r = i >> 4, c = i & 15;
            int gr = row0 + r;
            float4 v = make_float4(0.f, 0.f, 0.f, 0.f);
            if (gr < M)
                v = *(const float4*)((const char*)Xh + (size_t)gr * 256 + c * 16);
            *(float4*)(sA + r * RSB + c * 16) = v;
        }
    } else {
        #pragma unroll
        for (int it = 0; it < 8; it++) {
            int r  = wid + it * 16;
            int gr = row0 + r;
            float4 v = make_float4(0.f, 0.f, 0.f, 0.f);
            if (gr < M) v = *(const float4*)(Xf + (size_t)gr * CH + lane * 4);
            uint2 hh;
            hh.x = pack_bf2(__float2bfloat16(v.x), __float2bfloat16(v.y));
            hh.y = pack_bf2(__float2bfloat16(v.z), __float2bfloat16(v.w));
            *(uint2*)(sA + r * RSB + lane * 8) = hh;
        }
    }
    __syncthreads();

    const int warp_m = (wid & 3) * 32;
    const int wn8    = (wid >> 2) * 8;

    float acc[2][4][4];
    #pragma unroll
    for (int i = 0; i < 2; i++)
        #pragma unroll
        for (int j = 0; j < 4; j++)
            #pragma unroll
            for (int q = 0; q < 4; q++) acc[i][j][q] = 0.f;

    const uint32_t aA = smem_u32(sA);
    const int a_row  = lane & 15;
    const int a_koff = (lane & 16) ? 16 : 0;

    #pragma unroll
    for (int s = 0; s < 8; s++) {
        const int k0 = s * 16;
        // B global loads FIRST: latency overlaps A ldmatrix below
        const uint4* bp = Bf + (size_t)((wn8 + s) * 32 + lane) * 2;
        uint4 q0 = bp[0];
        uint4 q1 = bp[1];
        uint32_t a[2][4];
        #pragma unroll
        for (int fm = 0; fm < 2; fm++) {
            uint32_t addr = aA + (warp_m + fm * 16 + a_row) * RSB
                          + k0 * 2 + a_koff;
            LDMATRIX_X4(a[fm][0], a[fm][1], a[fm][2], a[fm][3], addr);
        }
        uint32_t b[4][2];
        b[0][0] = q0.x; b[0][1] = q0.y;
        b[1][0] = q0.z; b[1][1] = q0.w;
        b[2][0] = q1.x; b[2][1] = q1.y;
        b[3][0] = q1.z; b[3][1] = q1.w;
        #pragma unroll
        for (int fm = 0; fm < 2; fm++)
            #pragma unroll
            for (int fn = 0; fn < 4; fn++)
                MMA_BF16(acc[fm][fn], a[fm], b[fn]);
    }

    const int warp_n = (wid >> 2) * 32;
    const int erow = lane >> 2;
    const int ecol = (lane & 3) * 2;

    __syncthreads();
    #pragma unroll
    for (int fm = 0; fm < 2; fm++) {
        int r1 = warp_m + fm * 16 + erow;
        int r2 = r1 + 8;
        int g1 = row0 + r1, g2 = row0 + r2;
        float sc1 = 1.f, sc2 = 1.f;
        if (scaled) {
            sc1 = (g1 < M) ? rsqrtf((float)deg[g1] + 1.0f) : 0.f;
            sc2 = (g2 < M) ? rsqrtf((float)deg[g2] + 1.0f) : 0.f;
        }
        #pragma unroll
        for (int fn = 0; fn < 4; fn++) {
            int col = warp_n + fn * 8 + ecol;
            float b0 = bias ? bias[col]     : 0.f;
            float b1 = bias ? bias[col + 1] : 0.f;
            float2 v1, v2;
            v1.x = acc[fm][fn][0] + b0; v1.y = acc[fm][fn][1] + b1;
            v2.x = acc[fm][fn][2] + b0; v2.y = acc[fm][fn][3] + b1;
            if (relu) {
                v1.x = fmaxf(v1.x, 0.f); v1.y = fmaxf(v1.y, 0.f);
                v2.x = fmaxf(v2.x, 0.f); v2.y = fmaxf(v2.y, 0.f);
            }
            v1.x *= sc1; v1.y *= sc1;
            v2.x *= sc2; v2.y *= sc2;
            __nv_bfloat162 p1 = __float22bfloat162_rn(v1);
            __nv_bfloat162 p2 = __float22bfloat162_rn(v2);
            *(uint32_t*)(sA + r1 * RSB + col * 2) = *(uint32_t*)&p1;
            *(uint32_t*)(sA + r2 * RSB + col * 2) = *(uint32_t*)&p2;
        }
    }
    __syncthreads();
    #pragma unroll
    for (int i = tid; i < 2048; i += GEMM_THREADS) {
        int r = i >> 4, c = i & 15;
        int gr = row0 + r;
        if (gr < M)
            Yh[(size_t)gr * 16 + c] = *(uint4*)(sA + r * RSB + c * 16);
    }
}

// ---------------------------------------------------------------------------
// one-pass scan (block scan + atomic base) + invs + cnt=0   (launch #5)
// ---------------------------------------------------------------------------
#define SCAN_B 512
__global__ __launch_bounds__(SCAN_B)
void scan_atomic(const int* __restrict__ deg, int* __restrict__ csr_start,
                 float* __restrict__ invs, int* __restrict__ cnt,
                 int* __restrict__ cursor, int N) {
    __shared__ int sh[SCAN_B];
    __shared__ int sbase;
    int tid = threadIdx.x;
    int gid = blockIdx.x * SCAN_B + tid;
    int v = (gid < N) ? deg[gid] : 0;
    if (gid < N) {
        invs[gid] = rsqrtf((float)v + 1.0f);
        cnt[gid] = 0;
    }
    sh[tid] = v;
    __syncthreads();
    #pragma unroll
    for (int off = 1; off < SCAN_B; off <<= 1) {
        int t = (tid >= off) ? sh[tid - off] : 0;
        __syncthreads();
        if (tid >= off) sh[tid] += t;
        __syncthreads();
    }
    if (tid == SCAN_B - 1) sbase = atomicAdd(cursor, sh[SCAN_B - 1]);
    __syncthreads();
    if (gid < N) csr_start[gid] = sbase + sh[tid] - v;
}

__global__ void fill_csr(const void* __restrict__ eidx,
                         const int* __restrict__ csr_start,
                         int* __restrict__ cnt,
                         int* __restrict__ csr_src, int E) {
    int e = blockIdx.x * blockDim.x + threadIdx.x;
    if (e >= E) return;
    int r = load_index(eidx, e);
    int c = load_index(eidx, (long long)E + e);
    int pos = csr_start[c] + atomicAdd(&cnt[c], 1);
    csr_src[pos] = r;
}

// ---------------------------------------------------------------------------
// CSR gather (R14-proven): 2 nodes/warp, half-warp per node, lane=uint4,
// 4-deep unroll.
// ---------------------------------------------------------------------------
#define GACC(u) do { \
    float2 t0 = __bfloat1622float2(*(__nv_bfloat162*)&(u).x); \
    float2 t1 = __bfloat1622float2(*(__nv_bfloat162*)&(u).y); \
    float2 t2 = __bfloat1622float2(*(__nv_bfloat162*)&(u).z); \
    float2 t3 = __bfloat1622float2(*(__nv_bfloat162*)&(u).w); \
    a0 += t0.x; a1 += t0.y; a2 += t1.x; a3 += t1.y; \
    a4 += t2.x; a5 += t2.y; a6 += t3.x; a7 += t3.y; \
} while (0)

__global__ __launch_bounds__(256)
void gather_combine(const int* __restrict__ csr_start,
                    const int* __restrict__ deg,
                    const int* __restrict__ csr_src,
                    const uint4* __restrict__ hb,
                    const float* __restrict__ invs,
                    const float* __restrict__ bias,
                    uint4* __restrict__ outh, int N) {
    int warp = (blockIdx.x * blockDim.x + threadIdx.x) >> 5;
    int lane = threadIdx.x & 31;
    int node = warp * 2 + (lane >> 4);
    int hl   = lane & 15;
    if (node >= N) return;

    const int s0 = csr_start[node];
    const int e  = s0 + deg[node];
    const float invn = invs[node];
    const uint4* rowb = hb + hl;

    float a0, a1, a2, a3, a4, a5, a6, a7;
    {
        uint4 u = rowb[(size_t)node * 16];
        float2 t0 = __bfloat1622float2(*(__nv_bfloat162*)&u.x);
        float2 t1 = __bfloat1622float2(*(__nv_bfloat162*)&u.y);
        float2 t2 = __bfloat1622float2(*(__nv_bfloat162*)&u.z);
        float2 t3 = __bfloat1622float2(*(__nv_bfloat162*)&u.w);
        a0 = t0.x; a1 = t0.y; a2 = t1.x; a3 = t1.y;
        a4 = t2.x; a5 = t2.y; a6 = t3.x; a7 = t3.y;
    }

    int j = s0;
    for (; j + 4 <= e; j += 4) {
        int i0 = csr_src[j];
        int i1 = csr_src[j + 1];
        int i2 = csr_src[j + 2];
        int i3 = csr_src[j + 3];
        uint4 u0 = rowb[(size_t)i0 * 16];
        uint4 u1 = rowb[(size_t)i1 * 16];
        uint4 u2 = rowb[(size_t)i2 * 16];
        uint4 u3 = rowb[(size_t)i3 * 16];
        GACC(u0);
        GACC(u1);
        GACC(u2);
        GACC(u3);
    }
    for (; j < e; j++) {
        int i0 = csr_src[j];
        uint4 u0 = rowb[(size_t)i0 * 16];
        GACC(u0);
    }

    float4 b0 = *(const float4*)(bias + hl * 8);
    float4 b1 = *(const float4*)(bias + hl * 8 + 4);
    float2 o01, o23, o45, o67;
    o01.x = fmaxf(fmaf(a0, invn, b0.x), 0.f);
    o01.y = fmaxf(fmaf(a1, invn, b0.y), 0.f);
    o23.x = fmaxf(fmaf(a2, invn, b0.z), 0.f);
    o23.y = fmaxf(fmaf(a3, invn, b0.w), 0.f);
    o45.x = fmaxf(fmaf(a4, invn, b1.x), 0.f);
    o45.y = fmaxf(fmaf(a5, invn, b1.y), 0.f);
    o67.x = fmaxf(fmaf(a6, invn, b1.z), 0.f);
    o67.y = fmaxf(fmaf(a7, invn, b1.w), 0.f);
    __nv_bfloat162 p0 = __float22bfloat162_rn(o01);
    __nv_bfloat162 p1 = __float22bfloat162_rn(o23);
    __nv_bfloat162 p2 = __float22bfloat162_rn(o45);
    __nv_bfloat162 p3 = __float22bfloat162_rn(o67);
    uint4 ov;
    ov.x = *(uint32_t*)&p0;
    ov.y = *(uint32_t*)&p1;
    ov.z = *(uint32_t*)&p2;
    ov.w = *(uint32_t*)&p3;
    outh[(size_t)node * 16 + hl] = ov;
}

// ---------------------------------------------------------------------------
// fc2 (bf16 input) + per-graph pool
// ---------------------------------------------------------------------------
__global__ void fc2_pool(const __nv_bfloat16* __restrict__ h,
                         const void* __restrict__ batch,
                         const float* __restrict__ fcW2,
                         const float* __restrict__ fcb2,
                         float* __restrict__ gsum,
                         float* __restrict__ gcnt, int N) {
    int gw   = (blockIdx.x * blockDim.x + threadIdx.x) >> 5;
    int lane = threadIdx.x & 31;
    if (gw >= N) return;
    uint2 u = *(const uint2*)((const char*)h + (size_t)gw * 256 + lane * 8);
    float2 va = __bfloat1622float2(*(__nv_bfloat162*)&u.x);
    float2 vb = __bfloat1622float2(*(__nv_bfloat162*)&u.y);
    float4 w01 = *(const float4*)(fcW2 + 8 * lane);
    float4 w23 = *(const float4*)(fcW2 + 8 * lane + 4);
    float s0 = va.x * w01.x + va.y * w01.z + vb.x * w23.x + vb.y * w23.z;
    float s1 = va.x * w01.y + va.y * w01.w + vb.x * w23.y + vb.y * w23.w;
    #pragma unroll
    for (int o = 16; o > 0; o >>= 1) {
        s0 += __shfl_xor_sync(0xffffffffu, s0, o);
        s1 += __shfl_xor_sync(0xffffffffu, s1, o);
    }
    if (lane == 0) {
        int g = load_index(batch, gw);
        atomicAdd(&gsum[g * 2 + 0], s0 + fcb2[0]);
        atomicAdd(&gsum[g * 2 + 1], s1 + fcb2[1]);
        atomicAdd(&gcnt[g], 1.0f);
    }
}

__global__ void finalize(const float* gsum, const float* gcnt, float* out, int G) {
    int g = threadIdx.x;
    if (g >= G) return;
    float c  = fmaxf(gcnt[g], 1.0f);
    float p0 = gsum[g * 2 + 0] / c;
    float p1 = gsum[g * 2 + 1] / c;
    float m  = fmaxf(p0, p1);
    float e0 = expf(p0 - m);
    float e1 = expf(p1 - m);
    float inv = 1.0f / (e0 + e1);
    out[g * 2 + 0] = e0 * inv;
    out[g * 2 + 1] = e1 * inv;
}

// ---------------------------------------------------------------------------
// launch  (order: #4 = gemm_mma layer-1, the slot ncu profiles)
// ---------------------------------------------------------------------------
extern "C" void kernel_launch(void* const* d_in, const int* in_sizes, int n_in,
                              void* d_out, int out_size) {
    const float* x     = (const float*)d_in[0];
    const void*  eidx  = d_in[1];
    const void*  batch = d_in[2];
    const float* W1    = (const float*)d_in[3];
    const float* b1    = (const float*)d_in[4];
    const float* W2    = (const float*)d_in[5];
    const float* b2    = (const float*)d_in[6];
    const float* W3    = (const float*)d_in[7];
    const float* b3    = (const float*)d_in[8];
    const float* fcW1  = (const float*)d_in[9];
    const float* fcb1  = (const float*)d_in[10];
    const float* fcW2  = (const float*)d_in[11];
    const float* fcb2  = (const float*)d_in[12];

    const int N = in_sizes[0] / CH;
    const int E = in_sizes[1] / 2;
    const int G = out_size / 2;
    float* out = (float*)d_out;

    float *invs, *gsum, *gcnt;
    __nv_bfloat16 *bufAh, *bufBh;
    int *deg, *cnt, *csr_start, *csr_src, *cursor;
    uint32_t* wprep;
    cudaGetSymbolAddress((void**)&bufAh,     g_bufAh);
    cudaGetSymbolAddress((void**)&bufBh,     g_bufBh);
    cudaGetSymbolAddress((void**)&invs,      g_invs);
    cudaGetSymbolAddress((void**)&gsum,      g_gsum);
    cudaGetSymbolAddress((void**)&gcnt,      g_gcnt);
    cudaGetSymbolAddress((void**)&deg,       g_deg);
    cudaGetSymbolAddress((void**)&cnt,       g_cnt);
    cudaGetSymbolAddress((void**)&csr_start, g_csr_start);
    cudaGetSymbolAddress((void**)&csr_src,   g_csr_src);
    cudaGetSymbolAddress((void**)&cursor,    g_cursor);
    cudaGetSymbolAddress((void**)&wprep,     g_wprep);

    cudaFuncSetAttribute(gemm_mma, cudaFuncAttributeMaxDynamicSharedMemorySize,
                         SMEM_GEMM);

    const int nb = (N + SCAN_B - 1) / SCAN_B;
    const int gemm_blocks = (N + 127) / 128;
    const int gather_blocks = (N + 15) / 16;   // 2 nodes/warp, 8 warps/block

    WPtrs wp;
    wp.w[0] = W1; wp.w[1] = W2; wp.w[2] = W3; wp.w[3] = fcW1;

    detect_zero<<<(N + 255) / 256, 256>>>((const int*)eidx, deg, gsum, gcnt, N); // 1
    prep_weight4<<<dim3(32, 4), 256>>>(wp, wprep);                               // 2
    deg_kernel<<<(E + 255) / 256, 256>>>(eidx, deg, E);                          // 3

    // #4: layer-1 GEMM (f32 A path, scaled bf16 out)
    gemm_mma<<<gemm_blocks, GEMM_THREADS, SMEM_GEMM>>>(x, nullptr,
                                                       (const uint4*)wprep,
                                                       nullptr, deg,
                                                       (uint4*)bufBh, N, 0, 1);  // 4

    // CSR build
    scan_atomic<<<nb, SCAN_B>>>(deg, csr_start, invs, cnt, cursor, N);           // 5
    fill_csr<<<(E + 255) / 256, 256>>>(eidx, csr_start, cnt, csr_src, E);        // 6

    // layer 1 gather
    gather_combine<<<gather_blocks, 256>>>(csr_start, deg, csr_src,
                                           (const uint4*)bufBh, invs, b1,
                                           (uint4*)bufAh, N);                    // 7
    // layers 2..3
    const float* bs23[2] = { b2, b3 };
    const uint32_t* wp23[2] = { wprep + 8192, wprep + 2 * 8192 };
    for (int l = 0; l < 2; l++) {
        gemm_mma<<<gemm_blocks, GEMM_THREADS, SMEM_GEMM>>>(nullptr, bufAh,
                                                           (const uint4*)wp23[l],
                                                           nullptr, deg,
                                                           (uint4*)bufBh, N, 0, 1);
        gather_combine<<<gather_blocks, 256>>>(csr_start, deg, csr_src,
                                               (const uint4*)bufBh, invs, bs23[l],
                                               (uint4*)bufAh, N);
    }

    // fc1: bf16 in, bias+relu, bf16 out (no degree scale)
    gemm_mma<<<gemm_blocks, GEMM_THREADS, SMEM_GEMM>>>(nullptr, bufAh,
                                                       (const uint4*)(wprep + 3 * 8192),
                                                       fcb1, deg,
                                                       (uint4*)bufBh, N, 1, 0);

    fc2_pool<<<(N + 7) / 8, 256>>>(bufBh, batch, fcW2, fcb2, gsum, gcnt, N);
    finalize<<<1, (G + 31) / 32 * 32>>>(gsum, gcnt, out, G);
}